// round 3
// baseline (speedup 1.0000x reference)
#include <cuda_runtime.h>
#include <cuda_bf16.h>
#include <math.h>

// SpikeToCalciumDoubleExp: out[b,t] = sum_{j=0}^{K-1} kernel[j] * u[b, t+K-1-j]
// kernel[j] = (g1^{j+1} - g2^{j+1})/scale  with g = exp(-1/tau), tau1=20, tau2=2.
// Exact truncated-geometric recursion:
//   S(t) = g*S(t-1) + g*u[t+K-1] - g^{K+1}*u[t-1],  out = (S1 - S2)/scale
// Each thread seeds its (P,Q) state with a direct K-tap dot product, then runs
// the recursion for L outputs. ~8 FMA-ops/output instead of 242 -> memory bound.

#define THREADS 256
#define LPT 31                       // outputs per thread
#define CHUNK (THREADS * LPT)        // 7936 outputs per block
#define WIN (CHUNK + 128)            // input window (covers K<=125 tail)
#define SMW (WIN + ((WIN >> 6) << 2))// padded smem size (+4 floats per 64)

__device__ __forceinline__ int padidx(int j) {
    return j + ((j >> 6) << 2);
}

__global__ void __launch_bounds__(THREADS)
spike2calcium_kernel(const float* __restrict__ u, float* __restrict__ out,
                     int K, int T_out, int in_w) {
    __shared__ float  sm[SMW];
    __shared__ float2 wtab[128];

    const int tid = threadIdx.x;
    const int b   = blockIdx.y;
    const int t0  = blockIdx.x * CHUNK;

    // ---- filter constants (compile-time problem parameters) ----
    const float tau1 = 20.0f;   // TAU1 * HZ
    const float tau2 = 2.0f;    // TAU2 * HZ
    const float rr = tau1 / tau2;
    const float dd = tau1 - tau2;
    const float scale = powf(rr, -tau2 / dd) - powf(rr, -tau1 / dd);
    const float inv_scale = 1.0f / scale;
    const float g1 = expf(-1.0f / tau1);
    const float g2 = expf(-1.0f / tau2);

    // weight table: wtab[m-1] = { g1^m/scale, g2^m/scale },  m = 1..K
    if (tid < K) {
        float m = (float)(tid + 1);
        wtab[tid] = make_float2(expf(-m / tau1) * inv_scale,
                                expf(-m / tau2) * inv_scale);
    }

    // ---- cooperative load of input window into padded smem (float4) ----
    const float* row = u + (size_t)b * in_w + t0;
    const int wlen = min(WIN - 4, in_w - t0);   // elements available/needed
    const int nv = wlen >> 2;
    const float4* row4 = (const float4*)row;
    for (int v = tid; v < nv; v += THREADS) {
        float4 val = row4[v];
        int j = v << 2;
        *(float4*)&sm[padidx(j)] = val;         // stays inside one 64-blk, 16B aligned
    }
    for (int j = (nv << 2) + tid; j < wlen; j += THREADS)
        sm[padidx(j)] = row[j];
    __syncthreads();

    // ---- per-thread: seed + recursion ----
    const int base = tid * LPT;                 // local index of first output
    int nout = T_out - t0 - base;
    nout = min(nout, LPT);

    float o[LPT];
    if (nout > 0) {
        // seed: P = sum_m g1^m/scale * u[ts + K - m]  (r = K - m ascending local idx)
        float P = 0.0f, Q = 0.0f;
        #pragma unroll 4
        for (int r = 0; r < K; ++r) {
            float  x = sm[padidx(base + r)];
            float2 w = wtab[K - 1 - r];
            P = fmaf(w.x, x, P);
            Q = fmaf(w.y, x, Q);
        }
        o[0] = P - Q;

        const float cn1 = g1 * inv_scale;
        const float cn2 = g2 * inv_scale;
        const float co1 = powf(g1, (float)(K + 1)) * inv_scale;
        const float co2 = powf(g2, (float)(K + 1)) * inv_scale;  // underflows to 0 for tau2

        #pragma unroll
        for (int t = 1; t < LPT; ++t) {
            float xn = sm[padidx(base + t + K - 1)];
            float xo = sm[padidx(base + t - 1)];
            P = fmaf(g1, P, fmaf(cn1, xn, -co1 * xo));
            Q = fmaf(g2, Q, fmaf(cn2, xn, -co2 * xo));
            o[t] = P - Q;
        }
    }

    // ---- restage outputs through smem for coalesced float4 global stores ----
    __syncthreads();                            // done reading input window
    if (nout > 0) {
        #pragma unroll
        for (int t = 0; t < LPT; ++t)
            if (t < nout) sm[padidx(base + t)] = o[t];
    }
    __syncthreads();

    const int olen = min(CHUNK, T_out - t0);
    float* orow = out + (size_t)b * T_out + t0;
    const int nov = olen >> 2;
    for (int v = tid; v < nov; v += THREADS) {
        int j = v << 2;
        float4 val = *(const float4*)&sm[padidx(j)];
        *(float4*)(orow + j) = val;
    }
    for (int j = (nov << 2) + tid; j < olen; j += THREADS)
        orow[j] = sm[padidx(j)];
}

extern "C" void kernel_launch(void* const* d_in, const int* in_sizes, int n_in,
                              void* d_out, int out_size) {
    const float* u = (const float*)d_in[0];
    const int K = in_sizes[1];                      // 121
    // rows*(T_out+K-1) = in_sizes[0]; rows*T_out = out_size
    const int rows  = (in_sizes[0] - out_size) / (K - 1);   // 1024
    const int T_out = out_size / rows;                      // 30000
    const int in_w  = T_out + K - 1;                        // 30120

    const int n_chunks = (T_out + CHUNK - 1) / CHUNK;       // 4
    dim3 grid(n_chunks, rows);
    spike2calcium_kernel<<<grid, THREADS>>>(u, (float*)d_out, K, T_out, in_w);
}

// round 4
// speedup vs baseline: 1.0043x; 1.0043x over previous
#include <cuda_runtime.h>
#include <cuda_bf16.h>
#include <math.h>

// SpikeToCalciumDoubleExp: out[b,t] = sum_{j=0}^{K-1} kernel[j] * u[b, t+K-1-j]
// kernel[j] = (g1^{j+1} - g2^{j+1})/scale  with g = exp(-1/tau), tau1=20, tau2=2.
// Exact truncated-geometric recursion:
//   S(t) = g*S(t-1) + g*u[t+K-1] - g^{K+1}*u[t-1],  out = (S1 - S2)/scale
// Each thread seeds its (P,Q) state with a direct K-tap dot product, then runs
// the recursion for L outputs. ~8 FMA-ops/output instead of 242 -> memory bound.

#define THREADS 256
#define LPT 31                       // outputs per thread
#define CHUNK (THREADS * LPT)        // 7936 outputs per block
#define WIN (CHUNK + 128)            // input window (covers K<=125 tail)
#define SMW (WIN + ((WIN >> 6) << 2))// padded smem size (+4 floats per 64)

__device__ __forceinline__ int padidx(int j) {
    return j + ((j >> 6) << 2);
}

__global__ void __launch_bounds__(THREADS)
spike2calcium_kernel(const float* __restrict__ u, float* __restrict__ out,
                     int K, int T_out, int in_w) {
    __shared__ float  sm[SMW];
    __shared__ float2 wtab[128];

    const int tid = threadIdx.x;
    const int b   = blockIdx.y;
    const int t0  = blockIdx.x * CHUNK;

    // ---- filter constants (compile-time problem parameters) ----
    const float tau1 = 20.0f;   // TAU1 * HZ
    const float tau2 = 2.0f;    // TAU2 * HZ
    const float rr = tau1 / tau2;
    const float dd = tau1 - tau2;
    const float scale = powf(rr, -tau2 / dd) - powf(rr, -tau1 / dd);
    const float inv_scale = 1.0f / scale;
    const float g1 = expf(-1.0f / tau1);
    const float g2 = expf(-1.0f / tau2);

    // weight table: wtab[m-1] = { g1^m/scale, g2^m/scale },  m = 1..K
    if (tid < K) {
        float m = (float)(tid + 1);
        wtab[tid] = make_float2(expf(-m / tau1) * inv_scale,
                                expf(-m / tau2) * inv_scale);
    }

    // ---- cooperative load of input window into padded smem (float4) ----
    const float* row = u + (size_t)b * in_w + t0;
    const int wlen = min(WIN - 4, in_w - t0);   // elements available/needed
    const int nv = wlen >> 2;
    const float4* row4 = (const float4*)row;
    for (int v = tid; v < nv; v += THREADS) {
        float4 val = row4[v];
        int j = v << 2;
        *(float4*)&sm[padidx(j)] = val;         // stays inside one 64-blk, 16B aligned
    }
    for (int j = (nv << 2) + tid; j < wlen; j += THREADS)
        sm[padidx(j)] = row[j];
    __syncthreads();

    // ---- per-thread: seed + recursion ----
    const int base = tid * LPT;                 // local index of first output
    int nout = T_out - t0 - base;
    nout = min(nout, LPT);

    float o[LPT];
    if (nout > 0) {
        // seed: P = sum_m g1^m/scale * u[ts + K - m]  (r = K - m ascending local idx)
        float P = 0.0f, Q = 0.0f;
        #pragma unroll 4
        for (int r = 0; r < K; ++r) {
            float  x = sm[padidx(base + r)];
            float2 w = wtab[K - 1 - r];
            P = fmaf(w.x, x, P);
            Q = fmaf(w.y, x, Q);
        }
        o[0] = P - Q;

        const float cn1 = g1 * inv_scale;
        const float cn2 = g2 * inv_scale;
        const float co1 = powf(g1, (float)(K + 1)) * inv_scale;
        const float co2 = powf(g2, (float)(K + 1)) * inv_scale;  // underflows to 0 for tau2

        #pragma unroll
        for (int t = 1; t < LPT; ++t) {
            float xn = sm[padidx(base + t + K - 1)];
            float xo = sm[padidx(base + t - 1)];
            P = fmaf(g1, P, fmaf(cn1, xn, -co1 * xo));
            Q = fmaf(g2, Q, fmaf(cn2, xn, -co2 * xo));
            o[t] = P - Q;
        }
    }

    // ---- restage outputs through smem for coalesced float4 global stores ----
    __syncthreads();                            // done reading input window
    if (nout > 0) {
        #pragma unroll
        for (int t = 0; t < LPT; ++t)
            if (t < nout) sm[padidx(base + t)] = o[t];
    }
    __syncthreads();

    const int olen = min(CHUNK, T_out - t0);
    float* orow = out + (size_t)b * T_out + t0;
    const int nov = olen >> 2;
    for (int v = tid; v < nov; v += THREADS) {
        int j = v << 2;
        float4 val = *(const float4*)&sm[padidx(j)];
        *(float4*)(orow + j) = val;
    }
    for (int j = (nov << 2) + tid; j < olen; j += THREADS)
        orow[j] = sm[padidx(j)];
}

extern "C" void kernel_launch(void* const* d_in, const int* in_sizes, int n_in,
                              void* d_out, int out_size) {
    const float* u = (const float*)d_in[0];
    const int K = in_sizes[1];                      // 121
    // rows*(T_out+K-1) = in_sizes[0]; rows*T_out = out_size
    const int rows  = (in_sizes[0] - out_size) / (K - 1);   // 1024
    const int T_out = out_size / rows;                      // 30000
    const int in_w  = T_out + K - 1;                        // 30120

    const int n_chunks = (T_out + CHUNK - 1) / CHUNK;       // 4
    dim3 grid(n_chunks, rows);
    spike2calcium_kernel<<<grid, THREADS>>>(u, (float*)d_out, K, T_out, in_w);
}

// round 5
// speedup vs baseline: 1.1003x; 1.0955x over previous
#include <cuda_runtime.h>
#include <cuda_bf16.h>
#include <math.h>

// SpikeToCalciumDoubleExp: out[b,t] = sum_{j=0}^{K-1} kernel[j] * u[b, t+K-1-j]
// kernel[j] = (g1^{j+1} - g2^{j+1})/scale, g = exp(-1/tau), tau1=20, tau2=2, K=121.
//
// Exact truncated-geometric recursion (per channel):
//   S(t) = g*S(t-1) + (g/scale)*u[t+K-1] - (g^{K+1}/scale)*u[t-1]
// Seed via Horner (1 LDS + FMA per tap, no weight table, no index math):
//   H = 0; for r: H = H*g + u[base+r];  S = H*g/scale
// Fast channel (g2=e^-0.5): taps beyond ~40 weigh <1.2e-9 -> seed last 40 only;
// its recursion correction g2^(K+1)~3e-27 is dropped.
// Stride-31 per-lane smem access is bank-conflict-free (31 odd) -> no padding.

#define THREADS 256
#define LPT 31                       // outputs per thread
#define CHUNK (THREADS * LPT)        // 7936 outputs per block
#define WIN (CHUNK + 128)            // input window incl. K-1 + recursion lookahead

template<int KC>   // KC>0: compile-time K (unrolled, immediate-offset LDS); KC==0: runtime K
__global__ void __launch_bounds__(THREADS, 5)
spike2calcium_kernel(const float* __restrict__ u, float* __restrict__ out,
                     int Krt, int T_out, int in_w) {
    __shared__ float sm[WIN];

    const int K   = (KC > 0) ? KC : Krt;
    const int tid = threadIdx.x;
    const int b   = blockIdx.y;
    const int t0  = blockIdx.x * CHUNK;

    // ---- filter constants ----
    const float tau1 = 20.0f;   // TAU1 * HZ
    const float tau2 = 2.0f;    // TAU2 * HZ
    const float rr = tau1 / tau2;
    const float dd = tau1 - tau2;
    const float scale = powf(rr, -tau2 / dd) - powf(rr, -tau1 / dd);
    const float inv_scale = 1.0f / scale;
    const float g1 = expf(-1.0f / tau1);
    const float g2 = expf(-1.0f / tau2);

    // ---- cooperative load of input window (float4, coalesced, conflict-free) ----
    const float* row = u + (size_t)b * in_w + t0;
    const int wlen = min(WIN, in_w - t0);
    const int nv = wlen >> 2;
    const float4* row4 = (const float4*)row;
    for (int v = tid; v < nv; v += THREADS)
        *(float4*)&sm[v << 2] = row4[v];
    for (int j = (nv << 2) + tid; j < wlen; j += THREADS)
        sm[j] = row[j];
    __syncthreads();

    // ---- per-thread: Horner seed + exact recursion ----
    const int base = tid * LPT;
    int nout = T_out - t0 - base;
    nout = min(nout, LPT);

    float o[LPT];
    if (nout > 0) {
        float H1 = 0.0f, H2 = 0.0f;
        if (KC > 0) {
            // slow channel only: taps where g2-weight < ~1e-9
            #pragma unroll
            for (int r = 0; r < KC - 40; ++r)
                H1 = fmaf(H1, g1, sm[base + r]);
            // both channels for the most recent 40 taps
            #pragma unroll
            for (int r = KC - 40; r < KC; ++r) {
                float x = sm[base + r];
                H1 = fmaf(H1, g1, x);
                H2 = fmaf(H2, g2, x);
            }
        } else {
            for (int r = 0; r < K; ++r) {
                float x = sm[base + r];
                H1 = fmaf(H1, g1, x);
                H2 = fmaf(H2, g2, x);
            }
        }
        float P = H1 * g1 * inv_scale;   // scaled channel states
        float Q = H2 * g2 * inv_scale;
        o[0] = P - Q;

        const float cn1 = g1 * inv_scale;
        const float cn2 = g2 * inv_scale;
        const float co1 = expf(-(float)(K + 1) / tau1) * inv_scale;  // g1^(K+1)/scale

        #pragma unroll
        for (int t = 1; t < LPT; ++t) {
            float xn = sm[base + t + K - 1];
            float xo = sm[base + t - 1];
            P = fmaf(g1, P, fmaf(cn1, xn, -co1 * xo));
            Q = fmaf(g2, Q, cn2 * xn);   // g2^(K+1)/scale ~ 3e-27: dropped
            o[t] = P - Q;
        }
    }

    // ---- restage outputs through smem for coalesced float4 stores ----
    __syncthreads();                     // everyone done reading the input window
    if (nout > 0) {
        #pragma unroll
        for (int t = 0; t < LPT; ++t)
            if (t < nout) sm[base + t] = o[t];
    }
    __syncthreads();

    const int olen = min(CHUNK, T_out - t0);
    float* orow = out + (size_t)b * T_out + t0;
    const int nov = olen >> 2;
    for (int v = tid; v < nov; v += THREADS)
        *(float4*)(orow + (v << 2)) = *(const float4*)&sm[v << 2];
    for (int j = (nov << 2) + tid; j < olen; j += THREADS)
        orow[j] = sm[j];
}

extern "C" void kernel_launch(void* const* d_in, const int* in_sizes, int n_in,
                              void* d_out, int out_size) {
    const float* u = (const float*)d_in[0];
    const int K = in_sizes[1];                              // 121
    const int rows  = (in_sizes[0] - out_size) / (K - 1);   // 1024
    const int T_out = out_size / rows;                      // 30000
    const int in_w  = T_out + K - 1;                        // 30120

    const int n_chunks = (T_out + CHUNK - 1) / CHUNK;       // 4
    dim3 grid(n_chunks, rows);
    if (K == 121)
        spike2calcium_kernel<121><<<grid, THREADS>>>(u, (float*)d_out, K, T_out, in_w);
    else
        spike2calcium_kernel<0><<<grid, THREADS>>>(u, (float*)d_out, K, T_out, in_w);
}

// round 6
// speedup vs baseline: 1.6123x; 1.4654x over previous
#include <cuda_runtime.h>
#include <cuda_bf16.h>
#include <math.h>

// SpikeToCalciumDoubleExp: out[b,t] = sum_{j=0}^{K-1} kernel[j] * u[b, t+K-1-j]
// kernel[j] = (g1^{j+1} - g2^{j+1})/scale, g = exp(-1/tau), tau1=20, tau2=2, K=121.
//
// Per-channel state P(j) = (g/scale) * sum_{r=0}^{120} g^{120-r} u[j+r]; exact
// recursion P(j+1) = g*P(j) + (g/scale)*u[j+121] - (g^{122}/scale)*u[j].
//
// Seed decomposition (121 = 3*31 + 28): thread i's window = own chunk +
// chunks i+1, i+2 + 28-tap tail. Each thread computes ONE 31-tap Horner M_i
// over its own chunk, publishes to smem; seed = g^90*M_i + g^59*M_{i+1}
// + g^28*M_{i+2} + 28-tap tail. Fast channel (g2=e^-0.5): support is the last
// 40 taps only (r=81..120), done in the tail loop; g2^122 correction ~3e-27
// dropped. Stride-31 (odd) per-lane smem access is bank-conflict-free.

#define THREADS 256
#define LPT 31                       // outputs per thread
#define CHUNK (THREADS * LPT)        // 7936 outputs per block
#define WIN (CHUNK + 128)            // input window incl. K-1 lookahead
#define NM (THREADS + 2)             // M table incl. 2 overhang chunks

template<int KC>   // KC>0: compile-time K=121 fast path; KC==0: runtime-K fallback
__global__ void __launch_bounds__(THREADS, 5)
spike2calcium_kernel(const float* __restrict__ u, float* __restrict__ out,
                     int Krt, int T_out, int in_w) {
    __shared__ float sm[WIN];
    __shared__ float Msm[NM];

    const int K   = (KC > 0) ? KC : Krt;
    const int tid = threadIdx.x;
    const int b   = blockIdx.y;
    const int t0  = blockIdx.x * CHUNK;

    // ---- filter constants ----
    const float tau1 = 20.0f;   // TAU1 * HZ
    const float tau2 = 2.0f;    // TAU2 * HZ
    const float rr = tau1 / tau2;
    const float dd = tau1 - tau2;
    const float scale = powf(rr, -tau2 / dd) - powf(rr, -tau1 / dd);
    const float inv_scale = 1.0f / scale;
    const float g1 = expf(-1.0f / tau1);
    const float g2 = expf(-1.0f / tau2);
    const float cn1 = g1 * inv_scale;
    const float cn2 = g2 * inv_scale;

    // ---- phase 1: cooperative window load (float4, coalesced, conflict-free) ----
    const float* row = u + (size_t)b * in_w + t0;
    const int wlen = min(WIN, in_w - t0);
    const int nv = wlen >> 2;
    const float4* row4 = (const float4*)row;
    for (int v = tid; v < nv; v += THREADS)
        *(float4*)&sm[v << 2] = row4[v];
    for (int j = (nv << 2) + tid; j < wlen; j += THREADS)
        sm[j] = row[j];
    __syncthreads();

    const int base = tid * LPT;
    int nout = T_out - t0 - base;
    nout = min(nout, LPT);

    float o[LPT];

    if (KC > 0) {
        // ---- phase 2: own-chunk Horner M_i = sum_{r=0}^{30} g1^{30-r} x[base+r] ----
        float M = 0.0f;
        #pragma unroll
        for (int r = 0; r < LPT; ++r)
            M = fmaf(M, g1, sm[base + r]);
        Msm[tid] = M;
        if (tid < 2) {                      // overhang chunks 256, 257
            float Mo = 0.0f;
            const int ob = CHUNK + tid * LPT;
            #pragma unroll
            for (int r = 0; r < LPT; ++r)
                Mo = fmaf(Mo, g1, sm[ob + r]);
            Msm[THREADS + tid] = Mo;
        }

        // ---- phase 3 (pre-barrier, hides it): tail Horners, independent of M table
        // g2 channel: r = 81..120 (weights below ~3e-9 dropped)
        // g1 partial: r = 93..120  (the 28-tap remainder of the 121 window)
        float H1p = 0.0f, H2 = 0.0f;
        #pragma unroll
        for (int r = KC - 40; r < KC - 28; ++r)
            H2 = fmaf(H2, g2, sm[base + r]);
        #pragma unroll
        for (int r = KC - 28; r < KC; ++r) {
            float x = sm[base + r];
            H1p = fmaf(H1p, g1, x);
            H2  = fmaf(H2,  g2, x);
        }
        __syncthreads();                    // M table ready

        if (nout > 0) {
            const float c90 = expf(-90.0f / tau1);   // g1^90
            const float c59 = expf(-59.0f / tau1);   // g1^59
            const float c28 = expf(-28.0f / tau1);   // g1^28
            float M1 = Msm[tid + 1];
            float M2 = Msm[tid + 2];
            float U1 = fmaf(c90, M, fmaf(c59, M1, fmaf(c28, M2, H1p)));
            float P = cn1 * U1;
            float Q = cn2 * H2;
            o[0] = P - Q;

            const float co1 = expf(-(float)(KC + 1) / tau1) * inv_scale;  // g1^122/scale
            #pragma unroll
            for (int t = 1; t < LPT; ++t) {
                float xn = sm[base + t + KC - 1];
                float xo = sm[base + t - 1];
                P = fmaf(g1, P, fmaf(cn1, xn, -co1 * xo));
                Q = fmaf(g2, Q, cn2 * xn);     // g2^122/scale ~ 3e-27: dropped
                o[t] = P - Q;
            }
        }
    } else {
        // runtime-K fallback: direct full Horner seed + recursion
        __syncthreads();
        if (nout > 0) {
            float H1 = 0.0f, H2 = 0.0f;
            for (int r = 0; r < K; ++r) {
                float x = sm[base + r];
                H1 = fmaf(H1, g1, x);
                H2 = fmaf(H2, g2, x);
            }
            float P = H1 * cn1;
            float Q = H2 * cn2;
            o[0] = P - Q;
            const float co1 = expf(-(float)(K + 1) / tau1) * inv_scale;
            const float co2 = expf(-(float)(K + 1) / tau2) * inv_scale;
            #pragma unroll 8
            for (int t = 1; t < LPT; ++t) {
                float xn = sm[base + t + K - 1];
                float xo = sm[base + t - 1];
                P = fmaf(g1, P, fmaf(cn1, xn, -co1 * xo));
                Q = fmaf(g2, Q, fmaf(cn2, xn, -co2 * xo));
                o[t] = P - Q;
            }
        }
    }

    // ---- restage outputs through smem for coalesced float4 stores ----
    __syncthreads();                        // everyone done reading input window
    if (nout > 0) {
        #pragma unroll
        for (int t = 0; t < LPT; ++t)
            if (t < nout) sm[base + t] = o[t];
    }
    __syncthreads();

    const int olen = min(CHUNK, T_out - t0);
    float* orow = out + (size_t)b * T_out + t0;
    const int nov = olen >> 2;
    for (int v = tid; v < nov; v += THREADS)
        *(float4*)(orow + (v << 2)) = *(const float4*)&sm[v << 2];
    for (int j = (nov << 2) + tid; j < olen; j += THREADS)
        orow[j] = sm[j];
}

extern "C" void kernel_launch(void* const* d_in, const int* in_sizes, int n_in,
                              void* d_out, int out_size) {
    const float* u = (const float*)d_in[0];
    const int K = in_sizes[1];                              // 121
    const int rows  = (in_sizes[0] - out_size) / (K - 1);   // 1024
    const int T_out = out_size / rows;                      // 30000
    const int in_w  = T_out + K - 1;                        // 30120

    const int n_chunks = (T_out + CHUNK - 1) / CHUNK;       // 4
    dim3 grid(n_chunks, rows);
    if (K == 121)
        spike2calcium_kernel<121><<<grid, THREADS>>>(u, (float*)d_out, K, T_out, in_w);
    else
        spike2calcium_kernel<0><<<grid, THREADS>>>(u, (float*)d_out, K, T_out, in_w);
}

// round 7
// speedup vs baseline: 1.6752x; 1.0390x over previous
#include <cuda_runtime.h>
#include <cuda_bf16.h>
#include <math.h>

// SpikeToCalciumDoubleExp: out[b,t] = sum_{j=0}^{K-1} kernel[j] * u[b, t+K-1-j]
// kernel[j] = (g1^{j+1} - g2^{j+1})/scale, g = exp(-1/tau), tau1=20, tau2=2, K=121.
//
// Per-channel state P(j) = (g/scale) * sum_{r=0}^{120} g^{120-r} u[j+r]; exact
// recursion P(j+1) = g*P(j) + (g/scale)*u[j+121] - (g^{122}/scale)*u[j].
//
// Seed decomposition (121 = 3*31 + 28): each thread computes ONE 31-tap g1
// Horner M_i over its own chunk (loading those inputs into a register array
// x[31]), publishes M_i to smem; g1 seed = g^90*M_i + g^59*M_{i+1} + g^28*M_{i+2}
// + 28-tap tail (r=93..120). g2 channel (e^-0.5/tap): support truncated to the
// same 28-tap tail (dropped weight <= 1.7e-6). Recursion reuses x[] for its
// old-sample term (no LDS) and writes outputs back into x[] (slot t-1), so the
// array costs zero extra registers. Stride-31 (odd) smem access: conflict-free.

#define THREADS 256
#define LPT 31                       // outputs per thread
#define CHUNK (THREADS * LPT)        // 7936 outputs per block
#define WIN (CHUNK + 128)            // input window incl. K-1 lookahead
#define NM (THREADS + 2)             // M table incl. 2 overhang chunks

template<int KC>   // KC>0: compile-time K=121 fast path; KC==0: runtime-K fallback
__global__ void __launch_bounds__(THREADS, 5)
spike2calcium_kernel(const float* __restrict__ u, float* __restrict__ out,
                     int Krt, int T_out, int in_w) {
    __shared__ float sm[WIN];
    __shared__ float Msm[NM];

    const int K   = (KC > 0) ? KC : Krt;
    const int tid = threadIdx.x;
    const int b   = blockIdx.y;
    const int t0  = blockIdx.x * CHUNK;

    // ---- filter constants ----
    const float tau1 = 20.0f;   // TAU1 * HZ
    const float tau2 = 2.0f;    // TAU2 * HZ
    const float rr = tau1 / tau2;
    const float dd = tau1 - tau2;
    const float scale = powf(rr, -tau2 / dd) - powf(rr, -tau1 / dd);
    const float inv_scale = 1.0f / scale;
    const float g1 = expf(-1.0f / tau1);
    const float g2 = expf(-1.0f / tau2);
    const float cn1 = g1 * inv_scale;
    const float cn2 = g2 * inv_scale;

    // ---- phase 1: cooperative window load (float4, coalesced, conflict-free) ----
    const float* row = u + (size_t)b * in_w + t0;
    const int wlen = min(WIN, in_w - t0);
    const int nv = wlen >> 2;
    const float4* row4 = (const float4*)row;
    for (int v = tid; v < nv; v += THREADS)
        *(float4*)&sm[v << 2] = row4[v];
    for (int j = (nv << 2) + tid; j < wlen; j += THREADS)
        sm[j] = row[j];
    __syncthreads();

    const int base = tid * LPT;
    int nout = T_out - t0 - base;
    nout = min(nout, LPT);

    if (KC > 0) {
        // ---- phase 2: own-chunk Horner; keep inputs in register array x[] ----
        float x[LPT];
        float M = 0.0f;
        #pragma unroll
        for (int r = 0; r < LPT; ++r) {
            x[r] = sm[base + r];
            M = fmaf(M, g1, x[r]);
        }
        Msm[tid] = M;
        if (tid < 2) {                      // overhang chunks 256, 257
            float Mo = 0.0f;
            const int ob = CHUNK + tid * LPT;
            #pragma unroll
            for (int r = 0; r < LPT; ++r)
                Mo = fmaf(Mo, g1, sm[ob + r]);
            Msm[THREADS + tid] = Mo;
        }

        // ---- phase 3 (pre-barrier, hides it): 28-tap tail, both channels ----
        // r = 93..120: g1 exact remainder; g2 truncated support (drop < 1.7e-6)
        float H1p = 0.0f, H2 = 0.0f;
        #pragma unroll
        for (int r = KC - 28; r < KC; ++r) {
            float v = sm[base + r];
            H1p = fmaf(H1p, g1, v);
            H2  = fmaf(H2,  g2, v);
        }
        __syncthreads();                    // M table ready

        float o0 = 0.0f;
        if (nout > 0) {
            const float c90 = expf(-90.0f / tau1);   // g1^90
            const float c59 = expf(-59.0f / tau1);   // g1^59
            const float c28 = expf(-28.0f / tau1);   // g1^28
            float M1 = Msm[tid + 1];
            float M2 = Msm[tid + 2];
            float U1 = fmaf(c90, M, fmaf(c59, M1, fmaf(c28, M2, H1p)));
            float P = cn1 * U1;
            float Q = cn2 * H2;
            o0 = P - Q;

            const float co1 = expf(-(float)(KC + 1) / tau1) * inv_scale;  // g1^122/scale
            #pragma unroll
            for (int t = 1; t < LPT; ++t) {
                float xn = sm[base + t + KC - 1];
                float xo = x[t - 1];           // register, no LDS
                P = fmaf(g1, P, fmaf(cn1, xn, -co1 * xo));
                Q = fmaf(g2, Q, cn2 * xn);     // g2^122/scale ~ 3e-27: dropped
                x[t - 1] = P - Q;              // o[t] reuses x[t-1]'s slot
            }
        }

        // ---- restage outputs through smem for coalesced float4 stores ----
        __syncthreads();                    // everyone done reading input window
        if (nout > 0) {
            sm[base] = o0;
            #pragma unroll
            for (int t = 1; t < LPT; ++t)
                if (t < nout) sm[base + t] = x[t - 1];
        }
        __syncthreads();
    } else {
        // runtime-K fallback: direct full Horner seed + recursion
        float o[LPT];
        if (nout > 0) {
            float H1 = 0.0f, H2 = 0.0f;
            for (int r = 0; r < K; ++r) {
                float v = sm[base + r];
                H1 = fmaf(H1, g1, v);
                H2 = fmaf(H2, g2, v);
            }
            float P = H1 * cn1;
            float Q = H2 * cn2;
            o[0] = P - Q;
            const float co1 = expf(-(float)(K + 1) / tau1) * inv_scale;
            const float co2 = expf(-(float)(K + 1) / tau2) * inv_scale;
            #pragma unroll 8
            for (int t = 1; t < LPT; ++t) {
                float xn = sm[base + t + K - 1];
                float xo = sm[base + t - 1];
                P = fmaf(g1, P, fmaf(cn1, xn, -co1 * xo));
                Q = fmaf(g2, Q, fmaf(cn2, xn, -co2 * xo));
                o[t] = P - Q;
            }
        }
        __syncthreads();
        if (nout > 0) {
            #pragma unroll
            for (int t = 0; t < LPT; ++t)
                if (t < nout) sm[base + t] = o[t];
        }
        __syncthreads();
    }

    const int olen = min(CHUNK, T_out - t0);
    float* orow = out + (size_t)b * T_out + t0;
    const int nov = olen >> 2;
    for (int v = tid; v < nov; v += THREADS)
        *(float4*)(orow + (v << 2)) = *(const float4*)&sm[v << 2];
    for (int j = (nov << 2) + tid; j < olen; j += THREADS)
        orow[j] = sm[j];
}

extern "C" void kernel_launch(void* const* d_in, const int* in_sizes, int n_in,
                              void* d_out, int out_size) {
    const float* u = (const float*)d_in[0];
    const int K = in_sizes[1];                              // 121
    const int rows  = (in_sizes[0] - out_size) / (K - 1);   // 1024
    const int T_out = out_size / rows;                      // 30000
    const int in_w  = T_out + K - 1;                        // 30120

    const int n_chunks = (T_out + CHUNK - 1) / CHUNK;       // 4
    dim3 grid(n_chunks, rows);
    if (K == 121)
        spike2calcium_kernel<121><<<grid, THREADS>>>(u, (float*)d_out, K, T_out, in_w);
    else
        spike2calcium_kernel<0><<<grid, THREADS>>>(u, (float*)d_out, K, T_out, in_w);
}